// round 9
// baseline (speedup 1.0000x reference)
#include <cuda_runtime.h>
#include <cstdint>

#define T_LEN 1024
#define BATCH 2
#define EMB 1024
#define HEADS 16
#define HDIM 64
#define MROWS (T_LEN * BATCH)   // 2048
#define BH (BATCH * HEADS)      // 32

// ---------------- scratch (device globals; no allocation) ----------------
__device__ float sc_qkv[MROWS * 3 * EMB];   // g-stream: q | gk | gv   (2048 x 3072)
__device__ float sc_kvh[MROWS * 2 * EMB];   // h-stream: hk | hv       (2048 x 2048)
__device__ float sc_Sg[33554432];           // g scores / probs  [BH,T,T]
__device__ float sc_Sh[33554432];           // h scores / sample [BH,T,T]
__device__ float sc_ag[MROWS * EMB];        // merged g attention out [T*B, E]
__device__ float sc_ah[MROWS * EMB];        // merged h attention out

// ---------------- threefry2x32 (JAX, key = (0, 42)) -----------------------
// Full 20-round threefry2x32 returning BOTH output words.
// ks0 = 0, ks1 = 42, ks2 = 0x1BD11BDA ^ 0 ^ 42 = 0x1BD11BF0
static __device__ __forceinline__ uint2 threefry2x32_both(uint32_t c0, uint32_t c1) {
    const uint32_t ks1 = 42u;
    const uint32_t ks2 = 0x1BD11BF0u;
    uint32_t x0 = c0;            // + ks0 (=0)
    uint32_t x1 = c1 + ks1;
#define TF_R(r) { x0 += x1; x1 = __funnelshift_l(x1, x1, (r)); x1 ^= x0; }
    TF_R(13) TF_R(15) TF_R(26) TF_R(6)   x0 += ks1; x1 += ks2 + 1u;
    TF_R(17) TF_R(29) TF_R(16) TF_R(24)  x0 += ks2; x1 += 0u  + 2u;
    TF_R(13) TF_R(15) TF_R(26) TF_R(6)   x0 += 0u;  x1 += ks1 + 3u;
    TF_R(17) TF_R(29) TF_R(16) TF_R(24)  x0 += ks1; x1 += ks2 + 4u;
    TF_R(13) TF_R(15) TF_R(26) TF_R(6)   x0 += ks2; x1 += 0u  + 5u;
#undef TF_R
    return make_uint2(x0, x1);
}

// JAX partitionable mode (jax_threefry_partitionable=True, modern default):
// counts = hi/lo 32-bit words of 64-bit iota -> (0, i) for i < 2^32;
// 32-bit output = bits1 ^ bits2 (XOR of BOTH threefry output words).
static __device__ __forceinline__ uint32_t jax_bits_partitionable_xor(uint32_t idx) {
    uint2 w = threefry2x32_both(0u, idx);
    return w.x ^ w.y;
}

// ---------------- register-tiled SGEMM: C[M,N] = A[M,K] @ W[N,K]^T + bias ---
// epilogue: columns n < scale_cols multiplied by 0.125 (q * d^-0.5)
__global__ __launch_bounds__(256, 2) void sgemm_bias(
    const float* __restrict__ A, const float* __restrict__ W,
    const float* __restrict__ bias, float* __restrict__ C,
    int N, int K, int scale_cols)
{
    __shared__ float As[16][132];
    __shared__ float Bs[16][132];
    const int bm = blockIdx.y * 128;
    const int bn = blockIdx.x * 128;
    const int tid = threadIdx.x;
    const int tx = tid & 15, ty = tid >> 4;

    float acc[8][8];
#pragma unroll
    for (int i = 0; i < 8; i++)
#pragma unroll
        for (int j = 0; j < 8; j++) acc[i][j] = 0.f;

    const float* Ab = A + (size_t)bm * K;
    const float* Wb = W + (size_t)bn * K;

    for (int k0 = 0; k0 < K; k0 += 16) {
#pragma unroll
        for (int r = 0; r < 2; r++) {
            int idx = tid + r * 256;       // 0..511
            int row = idx >> 2;            // 0..127
            int kq  = (idx & 3) << 2;      // 0,4,8,12
            float4 va = *(const float4*)(Ab + (size_t)row * K + k0 + kq);
            As[kq+0][row] = va.x; As[kq+1][row] = va.y;
            As[kq+2][row] = va.z; As[kq+3][row] = va.w;
            float4 vb = *(const float4*)(Wb + (size_t)row * K + k0 + kq);
            Bs[kq+0][row] = vb.x; Bs[kq+1][row] = vb.y;
            Bs[kq+2][row] = vb.z; Bs[kq+3][row] = vb.w;
        }
        __syncthreads();
#pragma unroll
        for (int k = 0; k < 16; k++) {
            float ra[8], rb[8];
            *(float4*)(ra)     = *(const float4*)&As[k][ty * 8];
            *(float4*)(ra + 4) = *(const float4*)&As[k][ty * 8 + 4];
            *(float4*)(rb)     = *(const float4*)&Bs[k][tx * 8];
            *(float4*)(rb + 4) = *(const float4*)&Bs[k][tx * 8 + 4];
#pragma unroll
            for (int i = 0; i < 8; i++)
#pragma unroll
                for (int j = 0; j < 8; j++)
                    acc[i][j] = fmaf(ra[i], rb[j], acc[i][j]);
        }
        __syncthreads();
    }
#pragma unroll
    for (int i = 0; i < 8; i++) {
        int m = bm + ty * 8 + i;
#pragma unroll
        for (int j = 0; j < 8; j += 4) {
            int n = bn + tx * 8 + j;
            float4 o;
            o.x = acc[i][j+0] + bias[n+0];
            o.y = acc[i][j+1] + bias[n+1];
            o.z = acc[i][j+2] + bias[n+2];
            o.w = acc[i][j+3] + bias[n+3];
            if (n < scale_cols) { o.x *= 0.125f; o.y *= 0.125f; o.z *= 0.125f; o.w *= 0.125f; }
            *(float4*)(C + (size_t)m * N + n) = o;
        }
    }
}

// ---------------- dual-stream scores: Sg/Sh[bh,t,s] = sum_j q*k -----------
__global__ __launch_bounds__(256) void scores_kernel()
{
    __shared__ float Qs[64][65];   // [j][t]
    __shared__ float Ks[64][65];   // [j][s] (reused for gk then hk)
    const int s0 = blockIdx.x * 64;
    const int t0 = blockIdx.y * 64;
    const int bh = blockIdx.z;
    const int b = bh >> 4, hh = bh & 15;
    const int tid = threadIdx.x;
    const int tx = tid & 15, ty = tid >> 4;
    const int col = hh * HDIM;

#pragma unroll
    for (int r = 0; r < 4; r++) {
        int fi = tid + r * 256;
        int row = fi >> 4;
        int jq = (fi & 15) << 2;
        float4 q = *(const float4*)(sc_qkv + (size_t)((t0 + row) * BATCH + b) * 3072 + col + jq);
        Qs[jq+0][row] = q.x; Qs[jq+1][row] = q.y; Qs[jq+2][row] = q.z; Qs[jq+3][row] = q.w;
        float4 kg = *(const float4*)(sc_qkv + (size_t)((s0 + row) * BATCH + b) * 3072 + EMB + col + jq);
        Ks[jq+0][row] = kg.x; Ks[jq+1][row] = kg.y; Ks[jq+2][row] = kg.z; Ks[jq+3][row] = kg.w;
    }
    __syncthreads();

    float accg[4][4] = {};
#pragma unroll 8
    for (int j = 0; j < 64; j++) {
        float q0 = Qs[j][ty*4+0], q1 = Qs[j][ty*4+1], q2 = Qs[j][ty*4+2], q3 = Qs[j][ty*4+3];
        float k0 = Ks[j][tx*4+0], k1 = Ks[j][tx*4+1], k2 = Ks[j][tx*4+2], k3 = Ks[j][tx*4+3];
        accg[0][0] = fmaf(q0,k0,accg[0][0]); accg[0][1] = fmaf(q0,k1,accg[0][1]);
        accg[0][2] = fmaf(q0,k2,accg[0][2]); accg[0][3] = fmaf(q0,k3,accg[0][3]);
        accg[1][0] = fmaf(q1,k0,accg[1][0]); accg[1][1] = fmaf(q1,k1,accg[1][1]);
        accg[1][2] = fmaf(q1,k2,accg[1][2]); accg[1][3] = fmaf(q1,k3,accg[1][3]);
        accg[2][0] = fmaf(q2,k0,accg[2][0]); accg[2][1] = fmaf(q2,k1,accg[2][1]);
        accg[2][2] = fmaf(q2,k2,accg[2][2]); accg[2][3] = fmaf(q2,k3,accg[2][3]);
        accg[3][0] = fmaf(q3,k0,accg[3][0]); accg[3][1] = fmaf(q3,k1,accg[3][1]);
        accg[3][2] = fmaf(q3,k2,accg[3][2]); accg[3][3] = fmaf(q3,k3,accg[3][3]);
    }
    __syncthreads();

#pragma unroll
    for (int r = 0; r < 4; r++) {
        int fi = tid + r * 256;
        int row = fi >> 4;
        int jq = (fi & 15) << 2;
        float4 kh = *(const float4*)(sc_kvh + (size_t)((s0 + row) * BATCH + b) * 2048 + col + jq);
        Ks[jq+0][row] = kh.x; Ks[jq+1][row] = kh.y; Ks[jq+2][row] = kh.z; Ks[jq+3][row] = kh.w;
    }
    __syncthreads();

    float acch[4][4] = {};
#pragma unroll 8
    for (int j = 0; j < 64; j++) {
        float q0 = Qs[j][ty*4+0], q1 = Qs[j][ty*4+1], q2 = Qs[j][ty*4+2], q3 = Qs[j][ty*4+3];
        float k0 = Ks[j][tx*4+0], k1 = Ks[j][tx*4+1], k2 = Ks[j][tx*4+2], k3 = Ks[j][tx*4+3];
        acch[0][0] = fmaf(q0,k0,acch[0][0]); acch[0][1] = fmaf(q0,k1,acch[0][1]);
        acch[0][2] = fmaf(q0,k2,acch[0][2]); acch[0][3] = fmaf(q0,k3,acch[0][3]);
        acch[1][0] = fmaf(q1,k0,acch[1][0]); acch[1][1] = fmaf(q1,k1,acch[1][1]);
        acch[1][2] = fmaf(q1,k2,acch[1][2]); acch[1][3] = fmaf(q1,k3,acch[1][3]);
        acch[2][0] = fmaf(q2,k0,acch[2][0]); acch[2][1] = fmaf(q2,k1,acch[2][1]);
        acch[2][2] = fmaf(q2,k2,acch[2][2]); acch[2][3] = fmaf(q2,k3,acch[2][3]);
        acch[3][0] = fmaf(q3,k0,acch[3][0]); acch[3][1] = fmaf(q3,k1,acch[3][1]);
        acch[3][2] = fmaf(q3,k2,acch[3][2]); acch[3][3] = fmaf(q3,k3,acch[3][3]);
    }

    size_t obase = (size_t)bh * T_LEN * T_LEN;
#pragma unroll
    for (int i = 0; i < 4; i++) {
        size_t off = obase + (size_t)(t0 + ty * 4 + i) * T_LEN + s0 + tx * 4;
        float4 og = { accg[i][0], accg[i][1], accg[i][2], accg[i][3] };
        float4 oh = { acch[i][0], acch[i][1], acch[i][2], acch[i][3] };
        *(float4*)(sc_Sg + off) = og;
        *(float4*)(sc_Sh + off) = oh;
    }
}

// ---------------- row softmax (in place), row length 1024 ------------------
__global__ __launch_bounds__(256) void softmax_rows(float* __restrict__ S)
{
    __shared__ float red[8];
    size_t base = (size_t)blockIdx.x * T_LEN;
    int tid = threadIdx.x;
    float4 v = *(float4*)(S + base + tid * 4);
    float m = fmaxf(fmaxf(v.x, v.y), fmaxf(v.z, v.w));
#pragma unroll
    for (int o = 16; o > 0; o >>= 1) m = fmaxf(m, __shfl_xor_sync(0xffffffffu, m, o));
    if ((tid & 31) == 0) red[tid >> 5] = m;
    __syncthreads();
    float bm = red[0];
#pragma unroll
    for (int w = 1; w < 8; w++) bm = fmaxf(bm, red[w]);
    __syncthreads();
    float e0 = __expf(v.x - bm), e1 = __expf(v.y - bm);
    float e2 = __expf(v.z - bm), e3 = __expf(v.w - bm);
    float s = e0 + e1 + e2 + e3;
#pragma unroll
    for (int o = 16; o > 0; o >>= 1) s += __shfl_xor_sync(0xffffffffu, s, o);
    if ((tid & 31) == 0) red[tid >> 5] = s;
    __syncthreads();
    float tot = red[0] + red[1] + red[2] + red[3] + red[4] + red[5] + red[6] + red[7];
    float inv = 1.0f / tot;
    float4 o4 = { e0 * inv, e1 * inv, e2 * inv, e3 * inv };
    *(float4*)(S + base + tid * 4) = o4;
}

// ---------------- gumbel sample: softmax(scores + gumbel(u)) in place ------
__global__ __launch_bounds__(256) void sample_rows(float* __restrict__ S)
{
    __shared__ float red[8];
    size_t base = (size_t)blockIdx.x * T_LEN;
    int tid = threadIdx.x;
    float4 v = *(float4*)(S + base + tid * 4);
    uint32_t i0 = (uint32_t)base + (uint32_t)(tid * 4);
    float vals[4] = { v.x, v.y, v.z, v.w };
#pragma unroll
    for (int c = 0; c < 4; c++) {
        uint32_t y = jax_bits_partitionable_xor(i0 + (uint32_t)c);
        float u = __uint_as_float((y >> 9) | 0x3f800000u) - 1.0f;
        // noise = -log(-log(u + eps) + eps); inner log accurate (u near 1 cancels)
        float inner = -logf(u + 1e-20f) + 1e-20f;
        vals[c] += -__logf(inner);
    }
    float m = fmaxf(fmaxf(vals[0], vals[1]), fmaxf(vals[2], vals[3]));
#pragma unroll
    for (int o = 16; o > 0; o >>= 1) m = fmaxf(m, __shfl_xor_sync(0xffffffffu, m, o));
    if ((tid & 31) == 0) red[tid >> 5] = m;
    __syncthreads();
    float bm = red[0];
#pragma unroll
    for (int w = 1; w < 8; w++) bm = fmaxf(bm, red[w]);
    __syncthreads();
    float e[4];
    float s = 0.f;
#pragma unroll
    for (int c = 0; c < 4; c++) { e[c] = __expf(vals[c] - bm); s += e[c]; }
#pragma unroll
    for (int o = 16; o > 0; o >>= 1) s += __shfl_xor_sync(0xffffffffu, s, o);
    if ((tid & 31) == 0) red[tid >> 5] = s;
    __syncthreads();
    float tot = red[0] + red[1] + red[2] + red[3] + red[4] + red[5] + red[6] + red[7];
    float inv = 1.0f / tot;
    float4 o4 = { e[0] * inv, e[1] * inv, e[2] * inv, e[3] * inv };
    *(float4*)(S + base + tid * 4) = o4;
}

// ---------------- attn @ V, writes merged [T*B, E] layout ------------------
__global__ __launch_bounds__(256) void av_kernel(
    const float* __restrict__ P, const float* __restrict__ Vsrc,
    int ldv, int vcoloff, float* __restrict__ Out)
{
    __shared__ float Pt[64][65];   // [s][t]
    __shared__ float Vs[64][68];   // [s][j]
    const int t0 = blockIdx.x * 64;
    const int bh = blockIdx.y;
    const int b = bh >> 4, hh = bh & 15;
    const int tid = threadIdx.x;
    const int tx = tid & 15, ty = tid >> 4;

    float acc[4][4] = {};
    const float* Pb = P + (size_t)bh * T_LEN * T_LEN;

    for (int sk = 0; sk < T_LEN; sk += 64) {
#pragma unroll
        for (int r = 0; r < 4; r++) {
            int fi = tid + r * 256;
            int row = fi >> 4;
            int cq = (fi & 15) << 2;
            float4 p = *(const float4*)(Pb + (size_t)(t0 + row) * T_LEN + sk + cq);
            Pt[cq+0][row] = p.x; Pt[cq+1][row] = p.y; Pt[cq+2][row] = p.z; Pt[cq+3][row] = p.w;
            float4 vv = *(const float4*)(Vsrc + (size_t)((sk + row) * BATCH + b) * ldv
                                         + vcoloff + hh * HDIM + cq);
            *(float4*)&Vs[row][cq] = vv;
        }
        __syncthreads();
#pragma unroll 8
        for (int s = 0; s < 64; s++) {
            float p0 = Pt[s][ty*4+0], p1 = Pt[s][ty*4+1], p2 = Pt[s][ty*4+2], p3 = Pt[s][ty*4+3];
            float4 vv = *(const float4*)&Vs[s][tx * 4];
            acc[0][0] = fmaf(p0, vv.x, acc[0][0]); acc[0][1] = fmaf(p0, vv.y, acc[0][1]);
            acc[0][2] = fmaf(p0, vv.z, acc[0][2]); acc[0][3] = fmaf(p0, vv.w, acc[0][3]);
            acc[1][0] = fmaf(p1, vv.x, acc[1][0]); acc[1][1] = fmaf(p1, vv.y, acc[1][1]);
            acc[1][2] = fmaf(p1, vv.z, acc[1][2]); acc[1][3] = fmaf(p1, vv.w, acc[1][3]);
            acc[2][0] = fmaf(p2, vv.x, acc[2][0]); acc[2][1] = fmaf(p2, vv.y, acc[2][1]);
            acc[2][2] = fmaf(p2, vv.z, acc[2][2]); acc[2][3] = fmaf(p2, vv.w, acc[2][3]);
            acc[3][0] = fmaf(p3, vv.x, acc[3][0]); acc[3][1] = fmaf(p3, vv.y, acc[3][1]);
            acc[3][2] = fmaf(p3, vv.z, acc[3][2]); acc[3][3] = fmaf(p3, vv.w, acc[3][3]);
        }
        __syncthreads();
    }
#pragma unroll
    for (int i = 0; i < 4; i++) {
        float4 o = { acc[i][0], acc[i][1], acc[i][2], acc[i][3] };
        *(float4*)(Out + (size_t)((t0 + ty * 4 + i) * BATCH + b) * EMB + hh * HDIM + tx * 4) = o;
    }
}

// ---------------- launch ---------------------------------------------------
extern "C" void kernel_launch(void* const* d_in, const int* in_sizes, int n_in,
                              void* d_out, int out_size)
{
    (void)in_sizes; (void)n_in; (void)out_size;
    const float* g       = (const float*)d_in[0];
    const float* h       = (const float*)d_in[1];
    const float* g_in_w  = (const float*)d_in[2];
    const float* g_in_b  = (const float*)d_in[3];
    const float* h_in_w  = (const float*)d_in[4];
    const float* h_in_b  = (const float*)d_in[5];
    const float* g_out_w = (const float*)d_in[6];
    const float* g_out_b = (const float*)d_in[7];
    const float* h_out_w = (const float*)d_in[8];
    const float* h_out_b = (const float*)d_in[9];
    float* out = (float*)d_out;

    float *qkv, *kvh, *Sg, *Sh, *ag, *ah;
    cudaGetSymbolAddress((void**)&qkv, sc_qkv);
    cudaGetSymbolAddress((void**)&kvh, sc_kvh);
    cudaGetSymbolAddress((void**)&Sg,  sc_Sg);
    cudaGetSymbolAddress((void**)&Sh,  sc_Sh);
    cudaGetSymbolAddress((void**)&ag,  sc_ag);
    cudaGetSymbolAddress((void**)&ah,  sc_ah);

    dim3 blk(256);
    // input projections (q scaled by 1/8 in epilogue: cols < 1024 of g proj)
    sgemm_bias<<<dim3(3072 / 128, MROWS / 128), blk>>>(g, g_in_w, g_in_b, qkv, 3072, EMB, 1024);
    sgemm_bias<<<dim3(2048 / 128, MROWS / 128), blk>>>(h, h_in_w, h_in_b, kvh, 2048, EMB, 0);
    // dual scores
    scores_kernel<<<dim3(16, 16, 32), blk>>>();
    // softmax / gumbel sample (in place)
    softmax_rows<<<BH * T_LEN, 256>>>(Sg);
    sample_rows<<<BH * T_LEN, 256>>>(Sh);
    // attention @ V  (gv at col 2048 of qkv; hv at col 1024 of kvh)
    av_kernel<<<dim3(16, 32), blk>>>(Sg, qkv, 3072, 2048, ag);
    av_kernel<<<dim3(16, 32), blk>>>(Sh, kvh, 2048, 1024, ah);
    // output projections straight into d_out (g first, h second)
    sgemm_bias<<<dim3(1024 / 128, MROWS / 128), blk>>>(ag, g_out_w, g_out_b, out,               1024, EMB, 0);
    sgemm_bias<<<dim3(1024 / 128, MROWS / 128), blk>>>(ah, h_out_w, h_out_b, out + MROWS * EMB, 1024, EMB, 0);
}